// round 5
// baseline (speedup 1.0000x reference)
#include <cuda_runtime.h>
#include <math.h>
#include <stdint.h>

#define NN 100000
#define DD 256
#define HH 256
#define BB 128
#define EE 128
#define NSTEPS 5
#define G4H 1024
#define BH (BB*HH)
#define NCHUNK 8

// ---------------- scratch (static device globals; no allocations) ----------------
__device__ float g_xr[(size_t)NN*DD];      // tf32-rounded x
__device__ float g_y1[(size_t)NN*HH];      // FNN intermediate (tf32-rounded)
__device__ float g_hfeat[(size_t)NN*HH];   // FNN output
__device__ float g_w1r[DD*HH];             // W1 tf32-rounded, [k][n]
__device__ float g_w2r[HH*HH];             // W2 tf32-rounded, [k][n]
__device__ float g_e[NN];
__device__ float g_gates[BB*G4H];
__device__ float g_h[3*BH];
__device__ float g_c[3*BH];
__device__ float g_qstar[BB*2*HH];
__device__ float g_rpart[BB*NCHUNK*HH];
__device__ float g_denom[BB];
__device__ int   g_seg[BB+1];

// ---------------- helpers ----------------
__device__ __forceinline__ float sigf(float x) { return 1.f / (1.f + expf(-x)); }

__device__ __forceinline__ float rna_tf32(float f) {
    uint32_t r;
    asm("cvt.rna.tf32.f32 %0, %1;" : "=r"(r) : "f"(f));
    return __uint_as_float(r);
}

__device__ __forceinline__ void mma_tf32(float* c, const uint32_t* a, const uint32_t* b) {
    asm volatile(
        "mma.sync.aligned.m16n8k8.row.col.f32.tf32.tf32.f32 "
        "{%0,%1,%2,%3}, {%4,%5,%6,%7}, {%8,%9}, {%0,%1,%2,%3};"
        : "+f"(c[0]), "+f"(c[1]), "+f"(c[2]), "+f"(c[3])
        : "r"(a[0]), "r"(a[1]), "r"(a[2]), "r"(a[3]), "r"(b[0]), "r"(b[1]));
}

// ---------------- init / prep ----------------
__global__ void zero_state() {
    int i = blockIdx.x * blockDim.x + threadIdx.x;
    if (i < 3*BH) { g_h[i] = 0.f; g_c[i] = 0.f; }
    if (i < BB*2*HH) g_qstar[i] = 0.f;
}

__global__ void seg_bounds(const int* __restrict__ idx) {
    int b = threadIdx.x;
    if (b > BB) return;
    int lo = 0, hi = NN;
    while (lo < hi) { int mid = (lo + hi) >> 1; if (idx[mid] < b) lo = mid + 1; else hi = mid; }
    g_seg[b] = lo;
}

__global__ void round_x(const float* __restrict__ x) {
    size_t i = ((size_t)blockIdx.x * blockDim.x + threadIdx.x) * 4;
    if (i >= (size_t)NN*DD) return;
    float4 v = *(const float4*)&x[i];
    v.x = rna_tf32(v.x); v.y = rna_tf32(v.y);
    v.z = rna_tf32(v.z); v.w = rna_tf32(v.w);
    *(float4*)&g_xr[i] = v;
}

__global__ void round_mat(const float* __restrict__ W, float* __restrict__ out) {
    size_t i = ((size_t)blockIdx.x * blockDim.x + threadIdx.x) * 4;
    if (i >= (size_t)DD*HH) return;
    float4 v = *(const float4*)&W[i];
    v.x = rna_tf32(v.x); v.y = rna_tf32(v.y);
    v.z = rna_tf32(v.z); v.w = rna_tf32(v.w);
    *(float4*)&out[i] = v;
}

// ---------------- FNN GEMM: round-1 proven shell + tf32 mma.sync compute ----------------
// C = act(A @ W + bias), 128x128 tile, BK=16. As[k][m] stride 132, Bs[k][n] stride 128.
// PHASE 0: A=g_xr, C=g_y1, ELU + tf32 round. PHASE 1: A=g_y1, C=g_hfeat.
template<int PHASE>
__global__ void __launch_bounds__(256, 2)
fnn_gemm(const float* __restrict__ W, const float* __restrict__ bias) {
    const float* A = (PHASE == 0) ? g_xr : g_y1;
    float* C = (PHASE == 0) ? g_y1 : g_hfeat;
    __shared__ float As[16*132];   // [k][m], padded stride 132
    __shared__ float Bs[16*128];   // [k][n]
    int tid = threadIdx.x;
    int m0 = blockIdx.x * 128;
    int n0 = blockIdx.y * 128;
    int lane = tid & 31, wid = tid >> 5;
    int wm = wid & 3, wn = wid >> 2;   // warp tile: 32m x 64n
    int g = lane >> 2, tg = lane & 3;
    int arow = tid >> 2;               // 0..63
    int akq  = (tid & 3) * 4;          // 0,4,8,12
    int bk   = tid >> 5;               // 0..7
    int bnq  = (tid & 31) * 4;

    float acc[2][8][4];
    #pragma unroll
    for (int mf = 0; mf < 2; mf++)
        #pragma unroll
        for (int nf = 0; nf < 8; nf++)
            #pragma unroll
            for (int r = 0; r < 4; r++) acc[mf][nf][r] = 0.f;

    float4 pa0, pa1, pb0, pb1;
    {
        int gm0 = m0 + arow, gm1 = m0 + arow + 64;
        pa0 = (gm0 < NN) ? *(const float4*)&A[(size_t)gm0*DD + akq] : make_float4(0,0,0,0);
        pa1 = (gm1 < NN) ? *(const float4*)&A[(size_t)gm1*DD + akq] : make_float4(0,0,0,0);
        pb0 = *(const float4*)&W[(size_t)bk*HH + n0 + bnq];
        pb1 = *(const float4*)&W[(size_t)(bk+8)*HH + n0 + bnq];
    }
    for (int kt = 0; kt < DD; kt += 16) {
        As[(akq+0)*132+arow] = pa0.x; As[(akq+1)*132+arow] = pa0.y;
        As[(akq+2)*132+arow] = pa0.z; As[(akq+3)*132+arow] = pa0.w;
        As[(akq+0)*132+arow+64] = pa1.x; As[(akq+1)*132+arow+64] = pa1.y;
        As[(akq+2)*132+arow+64] = pa1.z; As[(akq+3)*132+arow+64] = pa1.w;
        *(float4*)&Bs[bk*128 + bnq]     = pb0;
        *(float4*)&Bs[(bk+8)*128 + bnq] = pb1;
        __syncthreads();
        int kn = kt + 16;
        if (kn < DD) {
            int gm0 = m0 + arow, gm1 = m0 + arow + 64;
            pa0 = (gm0 < NN) ? *(const float4*)&A[(size_t)gm0*DD + kn + akq] : make_float4(0,0,0,0);
            pa1 = (gm1 < NN) ? *(const float4*)&A[(size_t)gm1*DD + kn + akq] : make_float4(0,0,0,0);
            pb0 = *(const float4*)&W[(size_t)(kn+bk)*HH + n0 + bnq];
            pb1 = *(const float4*)&W[(size_t)(kn+bk+8)*HH + n0 + bnq];
        }
        // ---- tf32 mma compute on this 128x128x16 tile ----
        #pragma unroll
        for (int ks = 0; ks < 2; ks++) {
            int k0 = ks * 8;
            uint32_t a[2][4];
            #pragma unroll
            for (int mf = 0; mf < 2; mf++) {
                int rb = wm * 32 + mf * 16 + g;
                a[mf][0] = __float_as_uint(As[(k0+tg)*132 + rb]);
                a[mf][1] = __float_as_uint(As[(k0+tg)*132 + rb + 8]);
                a[mf][2] = __float_as_uint(As[(k0+tg+4)*132 + rb]);
                a[mf][3] = __float_as_uint(As[(k0+tg+4)*132 + rb + 8]);
            }
            uint32_t b[8][2];
            #pragma unroll
            for (int nf = 0; nf < 8; nf++) {
                int col = wn * 64 + nf * 8 + g;
                b[nf][0] = __float_as_uint(Bs[(k0+tg)*128 + col]);
                b[nf][1] = __float_as_uint(Bs[(k0+tg+4)*128 + col]);
            }
            #pragma unroll
            for (int mf = 0; mf < 2; mf++)
                #pragma unroll
                for (int nf = 0; nf < 8; nf++)
                    mma_tf32(acc[mf][nf], a[mf], b[nf]);
        }
        __syncthreads();
    }
    // epilogue
    #pragma unroll
    for (int mf = 0; mf < 2; mf++) {
        int r = wm * 32 + mf * 16 + g;
        int gm0 = m0 + r, gm1 = gm0 + 8;
        #pragma unroll
        for (int nf = 0; nf < 8; nf++) {
            int col = n0 + wn * 64 + nf * 8 + 2 * tg;
            float b0 = bias[col], b1 = bias[col + 1];
            float v00 = acc[mf][nf][0] + b0, v01 = acc[mf][nf][1] + b1;
            float v10 = acc[mf][nf][2] + b0, v11 = acc[mf][nf][3] + b1;
            if (PHASE == 0) {
                v00 = (v00 > 0.f) ? v00 : expm1f(v00); v00 = rna_tf32(v00);
                v01 = (v01 > 0.f) ? v01 : expm1f(v01); v01 = rna_tf32(v01);
                v10 = (v10 > 0.f) ? v10 : expm1f(v10); v10 = rna_tf32(v10);
                v11 = (v11 > 0.f) ? v11 : expm1f(v11); v11 = rna_tf32(v11);
            }
            if (gm0 < NN) *(float2*)&C[(size_t)gm0*HH + col] = make_float2(v00, v01);
            if (gm1 < NN) *(float2*)&C[(size_t)gm1*HH + col] = make_float2(v10, v11);
        }
    }
}

// ---------------- LSTM gates (round-2 proven) ----------------
__global__ void __launch_bounds__(128)
lstm_gates(int layer,
           const float* __restrict__ Wih, const float* __restrict__ Whh,
           const float* __restrict__ bih, const float* __restrict__ bhh) {
    __shared__ float As[8*768];
    __shared__ float Ws[32*68];
    const int K1 = (layer == 0) ? 2*HH : HH;
    const int K  = K1 + HH;
    const float* xin = (layer == 0) ? g_qstar : (g_h + (layer-1)*BH);
    const float* hin = g_h + layer*BH;
    int tid = threadIdx.x;
    int b0 = blockIdx.x * 8;
    int n0 = blockIdx.y * 64;
    for (int idx = tid; idx < 8*K; idx += 128) {
        int r = idx / K, k = idx - r*K;
        As[idx] = (k < K1) ? xin[(b0+r)*K1 + k] : hin[(b0+r)*HH + (k - K1)];
    }
    __syncthreads();
    int tx = tid & 15, ty = tid >> 4;
    int c0 = tx * 4;
    int wj = tid >> 3;
    int wk = (tid & 7) * 4;
    float acc[4] = {0.f, 0.f, 0.f, 0.f};
    for (int kt = 0; kt < K; kt += 32) {
        const float* Wsrc; int stride, kc;
        if (kt < K1) { Wsrc = Wih; stride = K1; kc = kt + wk; }
        else         { Wsrc = Whh; stride = HH; kc = kt - K1 + wk; }
        #pragma unroll
        for (int p = 0; p < 4; p++) {
            int j = p*16 + wj;
            float4 v = *(const float4*)&Wsrc[(size_t)(n0+j)*stride + kc];
            Ws[(wk+0)*68+j] = v.x; Ws[(wk+1)*68+j] = v.y;
            Ws[(wk+2)*68+j] = v.z; Ws[(wk+3)*68+j] = v.w;
        }
        __syncthreads();
        const float* arow = As + ty*K + kt;
        #pragma unroll
        for (int k = 0; k < 32; k++) {
            float a = arow[k];
            float4 bv = *(const float4*)&Ws[k*68 + c0];
            acc[0] = fmaf(a, bv.x, acc[0]);
            acc[1] = fmaf(a, bv.y, acc[1]);
            acc[2] = fmaf(a, bv.z, acc[2]);
            acc[3] = fmaf(a, bv.w, acc[3]);
        }
        __syncthreads();
    }
    int gb = b0 + ty;
    #pragma unroll
    for (int j = 0; j < 4; j++) {
        int gc = n0 + c0 + j;
        g_gates[gb*G4H + gc] = acc[j] + bih[gc] + bhh[gc];
    }
}

__global__ void lstm_cell(int layer) {
    int b = blockIdx.x, t = threadIdx.x;
    float* h = g_h + layer*BH;
    float* c = g_c + layer*BH;
    const float* g = g_gates + b*G4H;
    float gi = g[t], gf = g[HH + t], gg = g[2*HH + t], go = g[3*HH + t];
    float cn = sigf(gf) * c[b*HH + t] + sigf(gi) * tanhf(gg);
    float hn = sigf(go) * tanhf(cn);
    c[b*HH + t] = cn;
    h[b*HH + t] = hn;
    if (layer == 2) g_qstar[b*2*HH + t] = hn;
}

// ---------------- attention (round-2 proven) ----------------
__global__ void __launch_bounds__(256)
attn_logits(const int* __restrict__ bidx) {
    int n = blockIdx.x * 8 + (threadIdx.x >> 5);
    if (n >= NN) return;
    int lane = threadIdx.x & 31;
    const float* row = g_hfeat + (size_t)n*HH;
    const float* q = g_h + 2*BH + (size_t)bidx[n]*HH;
    float s = 0.f;
    #pragma unroll
    for (int j = 0; j < 8; j++) s = fmaf(row[lane + 32*j], q[lane + 32*j], s);
    #pragma unroll
    for (int o = 16; o > 0; o >>= 1) s += __shfl_xor_sync(0xffffffffu, s, o);
    if (lane == 0) g_e[n] = s;
}

__global__ void __launch_bounds__(256)
attn_softmax() {
    __shared__ float red[256];
    __shared__ float s_m;
    int b = blockIdx.x, t = threadIdx.x;
    int s = g_seg[b], e = g_seg[b+1];
    float mx = -INFINITY;
    for (int n = s + t; n < e; n += 256) mx = fmaxf(mx, g_e[n]);
    red[t] = mx;
    __syncthreads();
    for (int st = 128; st > 0; st >>= 1) {
        if (t < st) red[t] = fmaxf(red[t], red[t + st]);
        __syncthreads();
    }
    if (t == 0) {
        float m = red[0];
        if (!isfinite(m)) m = 0.f;
        s_m = m;
    }
    __syncthreads();
    float m = s_m;
    float lsum = 0.f;
    for (int n = s + t; n < e; n += 256) {
        float ex = expf(g_e[n] - m);
        g_e[n] = ex;
        lsum += ex;
    }
    __syncthreads();
    red[t] = lsum;
    __syncthreads();
    for (int st = 128; st > 0; st >>= 1) {
        if (t < st) red[t] += red[t + st];
        __syncthreads();
    }
    if (t == 0) g_denom[b] = red[0] + 1e-16f;
}

__global__ void __launch_bounds__(256)
attn_wsum() {
    int b = blockIdx.x, p = blockIdx.y, t = threadIdx.x;
    int s = g_seg[b], e = g_seg[b+1], len = e - s;
    int c0 = s + (len * p) / NCHUNK;
    int c1 = s + (len * (p+1)) / NCHUNK;
    float r0 = 0.f, r1 = 0.f, r2 = 0.f, r3 = 0.f;
    int n = c0;
    for (; n + 4 <= c1; n += 4) {
        r0 = fmaf(g_e[n],   g_hfeat[(size_t)n*HH + t],     r0);
        r1 = fmaf(g_e[n+1], g_hfeat[(size_t)(n+1)*HH + t], r1);
        r2 = fmaf(g_e[n+2], g_hfeat[(size_t)(n+2)*HH + t], r2);
        r3 = fmaf(g_e[n+3], g_hfeat[(size_t)(n+3)*HH + t], r3);
    }
    for (; n < c1; n++) r0 = fmaf(g_e[n], g_hfeat[(size_t)n*HH + t], r0);
    g_rpart[(size_t)(b*NCHUNK + p)*HH + t] = (r0 + r1) + (r2 + r3);
}

__global__ void __launch_bounds__(256)
attn_combine() {
    int b = blockIdx.x, t = threadIdx.x;
    float r = 0.f;
    #pragma unroll
    for (int p = 0; p < NCHUNK; p++) r += g_rpart[(size_t)(b*NCHUNK + p)*HH + t];
    g_qstar[b*2*HH + HH + t] = r / g_denom[b];
}

// ---------------- output projection ----------------
__global__ void out_proj(const float* __restrict__ W, const float* __restrict__ bvec,
                         float* __restrict__ out) {
    __shared__ float qrow[2*HH];
    int b = blockIdx.x, t = threadIdx.x;    // 128 threads
    #pragma unroll
    for (int i = 0; i < 4; i++) qrow[t + i*128] = g_qstar[b*2*HH + t + i*128];
    __syncthreads();
    float acc = 0.f;
    #pragma unroll 8
    for (int k = 0; k < 2*HH; k++) acc = fmaf(qrow[k], W[k*EE + t], acc);
    out[b*EE + t] = acc + bvec[t];
}

// ---------------- launch ----------------
extern "C" void kernel_launch(void* const* d_in, const int* in_sizes, int n_in,
                              void* d_out, int out_size) {
    const float* x    = (const float*)d_in[0];
    const int*   bidx = (const int*)  d_in[1];
    const float* W1   = (const float*)d_in[2];
    const float* b1   = (const float*)d_in[3];
    const float* W2   = (const float*)d_in[4];
    const float* b2   = (const float*)d_in[5];
    const float* Wih[3] = {(const float*)d_in[6],  (const float*)d_in[10], (const float*)d_in[14]};
    const float* Whh[3] = {(const float*)d_in[7],  (const float*)d_in[11], (const float*)d_in[15]};
    const float* bih[3] = {(const float*)d_in[8],  (const float*)d_in[12], (const float*)d_in[16]};
    const float* bhh[3] = {(const float*)d_in[9],  (const float*)d_in[13], (const float*)d_in[17]};
    const float* outW = (const float*)d_in[18];
    const float* outb = (const float*)d_in[19];
    float* out = (float*)d_out;

    zero_state<<<(3*BH + 255)/256, 256>>>();
    seg_bounds<<<1, 256>>>(bidx);
    round_x<<<(NN*DD/4 + 255)/256, 256>>>(x);
    round_mat<<<(DD*HH/4 + 255)/256, 256>>>(W1, g_w1r);
    round_mat<<<(DD*HH/4 + 255)/256, 256>>>(W2, g_w2r);

    dim3 gfnn((NN + 127)/128, HH/128);
    fnn_gemm<0><<<gfnn, 256>>>(g_w1r, b1);
    fnn_gemm<1><<<gfnn, 256>>>(g_w2r, b2);

    dim3 gg(BB/8, G4H/64);
    dim3 gw(BB, NCHUNK);
    for (int s = 0; s < NSTEPS; s++) {
        for (int l = 0; l < 3; l++) {
            lstm_gates<<<gg, 128>>>(l, Wih[l], Whh[l], bih[l], bhh[l]);
            lstm_cell<<<BB, HH>>>(l);
        }
        attn_logits<<<(NN + 7)/8, 256>>>(bidx);
        attn_softmax<<<BB, 256>>>();
        attn_wsum<<<gw, 256>>>();
        attn_combine<<<BB, 256>>>();
    }
    out_proj<<<BB, EE>>>(outW, outb, out);
}

// round 6
// speedup vs baseline: 1.2257x; 1.2257x over previous
#include <cuda_runtime.h>
#include <cuda_bf16.h>
#include <math.h>
#include <stdint.h>

#define NN 100000
#define DD 256
#define HH 256
#define BB 128
#define EE 128
#define NSTEPS 5
#define G4H 1024
#define BH (BB*HH)
#define NCHUNK 8

typedef unsigned long long ull;

// ---------------- scratch (static device globals; no allocations) ----------------
__device__ float g_y1[(size_t)NN*HH];      // FNN intermediate
__device__ float g_hfeat[(size_t)NN*HH];   // FNN output (fp32)
__device__ __nv_bfloat162 g_hfb16[(size_t)NN*HH/2];  // bf16 copy for logits pass
__device__ float g_e[NN];                  // attention logits / exp scratch
__device__ float g_gates[BB*G4H];          // LSTM gates
__device__ float g_h[3*BH];
__device__ float g_c[3*BH];
__device__ float g_qstar[BB*2*HH];
__device__ float g_rpart[BB*NCHUNK*HH];    // partial weighted sums
__device__ float g_denom[BB];
__device__ int   g_seg[BB+1];

// ---------------- helpers ----------------
__device__ __forceinline__ float sigf(float x) { return 1.f / (1.f + expf(-x)); }

__device__ __forceinline__ void ffma2(ull &d, ull a, ull b) {
    asm("fma.rn.f32x2 %0, %1, %2, %3;" : "=l"(d) : "l"(a), "l"(b), "l"(d));
}
__device__ __forceinline__ void unpack2(ull v, float &x, float &y) {
    asm("mov.b64 {%0, %1}, %2;" : "=f"(x), "=f"(y) : "l"(v));
}

// ---------------- init ----------------
__global__ void zero_state() {
    int i = blockIdx.x * blockDim.x + threadIdx.x;
    if (i < 3*BH) { g_h[i] = 0.f; g_c[i] = 0.f; }
    if (i < BB*2*HH) g_qstar[i] = 0.f;
}

__global__ void seg_bounds(const int* __restrict__ idx) {
    int b = threadIdx.x;
    if (b > BB) return;
    int lo = 0, hi = NN;
    while (lo < hi) { int mid = (lo + hi) >> 1; if (idx[mid] < b) lo = mid + 1; else hi = mid; }
    g_seg[b] = lo;
}

// ---------------- FNN GEMM: C = act(A @ W + bias), 128x128 tile, BK=16, FFMA2 ----------------
// As stores each A value as a duplicated pair -> FFMA2 operand loaded directly, no movs.
#define AST2 264   // smem stride in floats for duplicated-A rows (per k)
template<int PHASE>
__global__ void __launch_bounds__(256, 2)
fnn_gemm(const float* __restrict__ Ax, const float* __restrict__ W,
         const float* __restrict__ bias) {
    const float* A = (PHASE == 0) ? Ax : g_y1;
    float* C = (PHASE == 0) ? g_y1 : g_hfeat;
    __shared__ float As2[16*AST2];  // [k][2*m] duplicated pairs, 16.5KB
    __shared__ float Bs[16*128];    // [k][n]
    int tid = threadIdx.x;
    int m0 = blockIdx.x * 128;
    int n0 = blockIdx.y * 128;
    int tx = tid & 15, ty = tid >> 4;
    int c0 = tx * 8, r0 = ty * 8;
    int arow = tid >> 2;           // 0..63
    int akq  = (tid & 3) * 4;      // 0,4,8,12
    int bk   = tid >> 5;           // 0..7
    int bnq  = (tid & 31) * 4;

    ull acc[8][4];                 // 8 rows x 4 col-pairs (packed f32x2)
    #pragma unroll
    for (int i = 0; i < 8; i++)
        #pragma unroll
        for (int j = 0; j < 4; j++) acc[i][j] = 0ull;

    float4 pa0, pa1, pb0, pb1;
    {
        int gm0 = m0 + arow, gm1 = m0 + arow + 64;
        pa0 = (gm0 < NN) ? *(const float4*)&A[(size_t)gm0*DD + akq] : make_float4(0,0,0,0);
        pa1 = (gm1 < NN) ? *(const float4*)&A[(size_t)gm1*DD + akq] : make_float4(0,0,0,0);
        pb0 = *(const float4*)&W[(size_t)bk*HH + n0 + bnq];
        pb1 = *(const float4*)&W[(size_t)(bk+8)*HH + n0 + bnq];
    }
    for (int kt = 0; kt < DD; kt += 16) {
        // write duplicated pairs: As2[k][2*m] = As2[k][2*m+1] = A[m][k]
        *(float2*)&As2[(akq+0)*AST2 + 2*arow] = make_float2(pa0.x, pa0.x);
        *(float2*)&As2[(akq+1)*AST2 + 2*arow] = make_float2(pa0.y, pa0.y);
        *(float2*)&As2[(akq+2)*AST2 + 2*arow] = make_float2(pa0.z, pa0.z);
        *(float2*)&As2[(akq+3)*AST2 + 2*arow] = make_float2(pa0.w, pa0.w);
        *(float2*)&As2[(akq+0)*AST2 + 2*(arow+64)] = make_float2(pa1.x, pa1.x);
        *(float2*)&As2[(akq+1)*AST2 + 2*(arow+64)] = make_float2(pa1.y, pa1.y);
        *(float2*)&As2[(akq+2)*AST2 + 2*(arow+64)] = make_float2(pa1.z, pa1.z);
        *(float2*)&As2[(akq+3)*AST2 + 2*(arow+64)] = make_float2(pa1.w, pa1.w);
        *(float4*)&Bs[bk*128 + bnq]     = pb0;
        *(float4*)&Bs[(bk+8)*128 + bnq] = pb1;
        __syncthreads();
        int kn = kt + 16;
        if (kn < DD) {
            int gm0 = m0 + arow, gm1 = m0 + arow + 64;
            pa0 = (gm0 < NN) ? *(const float4*)&A[(size_t)gm0*DD + kn + akq] : make_float4(0,0,0,0);
            pa1 = (gm1 < NN) ? *(const float4*)&A[(size_t)gm1*DD + kn + akq] : make_float4(0,0,0,0);
            pb0 = *(const float4*)&W[(size_t)(kn+bk)*HH + n0 + bnq];
            pb1 = *(const float4*)&W[(size_t)(kn+bk+8)*HH + n0 + bnq];
        }
        #pragma unroll
        for (int k = 0; k < 16; k++) {
            const ull* abase = (const ull*)&As2[k*AST2 + 2*r0];
            ulonglong2 a01 = *(const ulonglong2*)(abase + 0);
            ulonglong2 a23 = *(const ulonglong2*)(abase + 2);
            ulonglong2 a45 = *(const ulonglong2*)(abase + 4);
            ulonglong2 a67 = *(const ulonglong2*)(abase + 6);
            ulonglong2 bq0 = *(const ulonglong2*)&Bs[k*128 + c0];
            ulonglong2 bq1 = *(const ulonglong2*)&Bs[k*128 + c0 + 4];
            ull ap[8] = {a01.x, a01.y, a23.x, a23.y, a45.x, a45.y, a67.x, a67.y};
            #pragma unroll
            for (int i = 0; i < 8; i++) {
                ffma2(acc[i][0], ap[i], bq0.x);
                ffma2(acc[i][1], ap[i], bq0.y);
                ffma2(acc[i][2], ap[i], bq1.x);
                ffma2(acc[i][3], ap[i], bq1.y);
            }
        }
        __syncthreads();
    }
    float bv[8];
    #pragma unroll
    for (int j = 0; j < 8; j++) bv[j] = bias[n0 + c0 + j];
    #pragma unroll
    for (int i = 0; i < 8; i++) {
        int gm = m0 + r0 + i;
        if (gm < NN) {
            float o[8];
            #pragma unroll
            for (int j = 0; j < 4; j++) {
                float x, y;
                unpack2(acc[i][j], x, y);
                float v0 = x + bv[2*j], v1 = y + bv[2*j+1];
                if (PHASE == 0) {
                    v0 = (v0 > 0.f) ? v0 : expm1f(v0);
                    v1 = (v1 > 0.f) ? v1 : expm1f(v1);
                }
                o[2*j] = v0; o[2*j+1] = v1;
            }
            *(float4*)&C[(size_t)gm*HH + n0 + c0]     = *(float4*)&o[0];
            *(float4*)&C[(size_t)gm*HH + n0 + c0 + 4] = *(float4*)&o[4];
            if (PHASE == 1) {
                // bf16 copy for the logits pass (packed bf16x2 x4 = 16B)
                __nv_bfloat162 p0 = __float22bfloat162_rn(make_float2(o[0], o[1]));
                __nv_bfloat162 p1 = __float22bfloat162_rn(make_float2(o[2], o[3]));
                __nv_bfloat162 p2 = __float22bfloat162_rn(make_float2(o[4], o[5]));
                __nv_bfloat162 p3 = __float22bfloat162_rn(make_float2(o[6], o[7]));
                uint4 pk;
                pk.x = *(uint32_t*)&p0; pk.y = *(uint32_t*)&p1;
                pk.z = *(uint32_t*)&p2; pk.w = *(uint32_t*)&p3;
                *(uint4*)&g_hfb16[((size_t)gm*HH + n0 + c0) >> 1] = pk;
            }
        }
    }
}

// ---------------- LSTM gates (round-2 proven) ----------------
__global__ void __launch_bounds__(128)
lstm_gates(int layer,
           const float* __restrict__ Wih, const float* __restrict__ Whh,
           const float* __restrict__ bih, const float* __restrict__ bhh) {
    __shared__ float As[8*768];
    __shared__ float Ws[32*68];
    const int K1 = (layer == 0) ? 2*HH : HH;
    const int K  = K1 + HH;
    const float* xin = (layer == 0) ? g_qstar : (g_h + (layer-1)*BH);
    const float* hin = g_h + layer*BH;
    int tid = threadIdx.x;
    int b0 = blockIdx.x * 8;
    int n0 = blockIdx.y * 64;
    for (int idx = tid; idx < 8*K; idx += 128) {
        int r = idx / K, k = idx - r*K;
        As[idx] = (k < K1) ? xin[(b0+r)*K1 + k] : hin[(b0+r)*HH + (k - K1)];
    }
    __syncthreads();
    int tx = tid & 15, ty = tid >> 4;
    int c0 = tx * 4;
    int wj = tid >> 3;
    int wk = (tid & 7) * 4;
    float acc[4] = {0.f, 0.f, 0.f, 0.f};
    for (int kt = 0; kt < K; kt += 32) {
        const float* Wsrc; int stride, kc;
        if (kt < K1) { Wsrc = Wih; stride = K1; kc = kt + wk; }
        else         { Wsrc = Whh; stride = HH; kc = kt - K1 + wk; }
        #pragma unroll
        for (int p = 0; p < 4; p++) {
            int j = p*16 + wj;
            float4 v = *(const float4*)&Wsrc[(size_t)(n0+j)*stride + kc];
            Ws[(wk+0)*68+j] = v.x; Ws[(wk+1)*68+j] = v.y;
            Ws[(wk+2)*68+j] = v.z; Ws[(wk+3)*68+j] = v.w;
        }
        __syncthreads();
        const float* arow = As + ty*K + kt;
        #pragma unroll
        for (int k = 0; k < 32; k++) {
            float a = arow[k];
            float4 bv = *(const float4*)&Ws[k*68 + c0];
            acc[0] = fmaf(a, bv.x, acc[0]);
            acc[1] = fmaf(a, bv.y, acc[1]);
            acc[2] = fmaf(a, bv.z, acc[2]);
            acc[3] = fmaf(a, bv.w, acc[3]);
        }
        __syncthreads();
    }
    int gb = b0 + ty;
    #pragma unroll
    for (int j = 0; j < 4; j++) {
        int gc = n0 + c0 + j;
        g_gates[gb*G4H + gc] = acc[j] + bih[gc] + bhh[gc];
    }
}

__global__ void lstm_cell(int layer) {
    int b = blockIdx.x, t = threadIdx.x;
    float* h = g_h + layer*BH;
    float* c = g_c + layer*BH;
    const float* g = g_gates + b*G4H;
    float gi = g[t], gf = g[HH + t], gg = g[2*HH + t], go = g[3*HH + t];
    float cn = sigf(gf) * c[b*HH + t] + sigf(gi) * tanhf(gg);
    float hn = sigf(go) * tanhf(cn);
    c[b*HH + t] = cn;
    h[b*HH + t] = hn;
    if (layer == 2) g_qstar[b*2*HH + t] = hn;
}

// ---------------- attention ----------------
// k1: e[n] = dot(hfeat_bf16[n], q[batch_idxs[n]]); one warp per row, 16B/lane
__global__ void __launch_bounds__(256)
attn_logits(const int* __restrict__ bidx) {
    int n = blockIdx.x * 8 + (threadIdx.x >> 5);
    if (n >= NN) return;
    int lane = threadIdx.x & 31;
    const uint4* row = (const uint4*)(g_hfb16 + (size_t)n * (HH/2));
    const float4* q = (const float4*)(g_h + 2*BH + (size_t)bidx[n]*HH);
    uint4 v = row[lane];
    float4 q0 = q[2*lane], q1 = q[2*lane + 1];
    float2 h0 = __bfloat1622float2(*(__nv_bfloat162*)&v.x);
    float2 h1 = __bfloat1622float2(*(__nv_bfloat162*)&v.y);
    float2 h2 = __bfloat1622float2(*(__nv_bfloat162*)&v.z);
    float2 h3 = __bfloat1622float2(*(__nv_bfloat162*)&v.w);
    float s = 0.f;
    s = fmaf(h0.x, q0.x, s); s = fmaf(h0.y, q0.y, s);
    s = fmaf(h1.x, q0.z, s); s = fmaf(h1.y, q0.w, s);
    s = fmaf(h2.x, q1.x, s); s = fmaf(h2.y, q1.y, s);
    s = fmaf(h3.x, q1.z, s); s = fmaf(h3.y, q1.w, s);
    #pragma unroll
    for (int o = 16; o > 0; o >>= 1) s += __shfl_xor_sync(0xffffffffu, s, o);
    if (lane == 0) g_e[n] = s;
}

__global__ void __launch_bounds__(256)
attn_softmax() {
    __shared__ float red[256];
    __shared__ float s_m;
    int b = blockIdx.x, t = threadIdx.x;
    int s = g_seg[b], e = g_seg[b+1];
    float mx = -INFINITY;
    for (int n = s + t; n < e; n += 256) mx = fmaxf(mx, g_e[n]);
    red[t] = mx;
    __syncthreads();
    for (int st = 128; st > 0; st >>= 1) {
        if (t < st) red[t] = fmaxf(red[t], red[t + st]);
        __syncthreads();
    }
    if (t == 0) {
        float m = red[0];
        if (!isfinite(m)) m = 0.f;
        s_m = m;
    }
    __syncthreads();
    float m = s_m;
    float lsum = 0.f;
    for (int n = s + t; n < e; n += 256) {
        float ex = expf(g_e[n] - m);
        g_e[n] = ex;
        lsum += ex;
    }
    __syncthreads();
    red[t] = lsum;
    __syncthreads();
    for (int st = 128; st > 0; st >>= 1) {
        if (t < st) red[t] += red[t + st];
        __syncthreads();
    }
    if (t == 0) g_denom[b] = red[0] + 1e-16f;
}

__global__ void __launch_bounds__(256)
attn_wsum() {
    int b = blockIdx.x, p = blockIdx.y, t = threadIdx.x;
    int s = g_seg[b], e = g_seg[b+1], len = e - s;
    int c0 = s + (len * p) / NCHUNK;
    int c1 = s + (len * (p+1)) / NCHUNK;
    float r0 = 0.f, r1 = 0.f, r2 = 0.f, r3 = 0.f;
    int n = c0;
    for (; n + 4 <= c1; n += 4) {
        r0 = fmaf(g_e[n],   g_hfeat[(size_t)n*HH + t],     r0);
        r1 = fmaf(g_e[n+1], g_hfeat[(size_t)(n+1)*HH + t], r1);
        r2 = fmaf(g_e[n+2], g_hfeat[(size_t)(n+2)*HH + t], r2);
        r3 = fmaf(g_e[n+3], g_hfeat[(size_t)(n+3)*HH + t], r3);
    }
    for (; n < c1; n++) r0 = fmaf(g_e[n], g_hfeat[(size_t)n*HH + t], r0);
    g_rpart[(size_t)(b*NCHUNK + p)*HH + t] = (r0 + r1) + (r2 + r3);
}

__global__ void __launch_bounds__(256)
attn_combine() {
    int b = blockIdx.x, t = threadIdx.x;
    float r = 0.f;
    #pragma unroll
    for (int p = 0; p < NCHUNK; p++) r += g_rpart[(size_t)(b*NCHUNK + p)*HH + t];
    g_qstar[b*2*HH + HH + t] = r / g_denom[b];
}

// ---------------- output projection ----------------
__global__ void out_proj(const float* __restrict__ W, const float* __restrict__ bvec,
                         float* __restrict__ out) {
    __shared__ float qrow[2*HH];
    int b = blockIdx.x, t = threadIdx.x;    // 128 threads
    #pragma unroll
    for (int i = 0; i < 4; i++) qrow[t + i*128] = g_qstar[b*2*HH + t + i*128];
    __syncthreads();
    float acc = 0.f;
    #pragma unroll 8
    for (int k = 0; k < 2*HH; k++) acc = fmaf(qrow[k], W[k*EE + t], acc);
    out[b*EE + t] = acc + bvec[t];
}

// ---------------- launch ----------------
extern "C" void kernel_launch(void* const* d_in, const int* in_sizes, int n_in,
                              void* d_out, int out_size) {
    const float* x    = (const float*)d_in[0];
    const int*   bidx = (const int*)  d_in[1];
    const float* W1   = (const float*)d_in[2];
    const float* b1   = (const float*)d_in[3];
    const float* W2   = (const float*)d_in[4];
    const float* b2   = (const float*)d_in[5];
    const float* Wih[3] = {(const float*)d_in[6],  (const float*)d_in[10], (const float*)d_in[14]};
    const float* Whh[3] = {(const float*)d_in[7],  (const float*)d_in[11], (const float*)d_in[15]};
    const float* bih[3] = {(const float*)d_in[8],  (const float*)d_in[12], (const float*)d_in[16]};
    const float* bhh[3] = {(const float*)d_in[9],  (const float*)d_in[13], (const float*)d_in[17]};
    const float* outW = (const float*)d_in[18];
    const float* outb = (const float*)d_in[19];
    float* out = (float*)d_out;

    zero_state<<<(3*BH + 255)/256, 256>>>();
    seg_bounds<<<1, 256>>>(bidx);

    dim3 gfnn((NN + 127)/128, HH/128);
    fnn_gemm<0><<<gfnn, 256>>>(x, W1, b1);
    fnn_gemm<1><<<gfnn, 256>>>(x, W2, b2);   // A ignored in phase 1 (reads g_y1)

    dim3 gg(BB/8, G4H/64);
    dim3 gw(BB, NCHUNK);
    for (int s = 0; s < NSTEPS; s++) {
        for (int l = 0; l < 3; l++) {
            lstm_gates<<<gg, 128>>>(l, Wih[l], Whh[l], bih[l], bhh[l]);
            lstm_cell<<<BB, HH>>>(l);
        }
        attn_logits<<<(NN + 7)/8, 256>>>(bidx);
        attn_softmax<<<BB, 256>>>();
        attn_wsum<<<gw, 256>>>();
        attn_combine<<<BB, 256>>>();
    }
    out_proj<<<BB, EE>>>(outW, outb, out);
}

// round 7
// speedup vs baseline: 1.4708x; 1.2000x over previous
#include <cuda_runtime.h>
#include <math.h>
#include <stdint.h>

#define NN 100000
#define DD 256
#define HH 256
#define BB 128
#define EE 128
#define NSTEPS 5
#define G4H 1024
#define BH (BB*HH)
#define NCHUNK 16
#define TS 64

typedef unsigned long long ull;

// ---------------- scratch (static device globals; no allocations) ----------------
__device__ float g_y1[(size_t)NN*HH];      // FNN intermediate
__device__ float g_hfeat[(size_t)NN*HH];   // FNN output
__device__ float g_gates[BB*G4H];          // LSTM gates
__device__ float g_h[3*BH];
__device__ float g_c[3*BH];
__device__ float g_qstar[BB*2*HH];
__device__ float g_rpart[(size_t)BB*NCHUNK*HH];  // partial weighted sums
__device__ float g_spart[BB*NCHUNK];       // partial exp-sums
__device__ float g_mpart[BB*NCHUNK];       // partial maxes
__device__ int   g_seg[BB+1];

// ---------------- helpers ----------------
__device__ __forceinline__ float sigf(float x) { return 1.f / (1.f + expf(-x)); }

__device__ __forceinline__ void ffma2(ull &d, ull a, ull b) {
    asm("fma.rn.f32x2 %0, %1, %2, %3;" : "=l"(d) : "l"(a), "l"(b), "l"(d));
}
__device__ __forceinline__ ull bcast2(float a) {
    ull r;
    asm("mov.b64 %0, {%1, %1};" : "=l"(r) : "f"(a));
    return r;
}
__device__ __forceinline__ void unpack2(ull v, float &x, float &y) {
    asm("mov.b64 {%0, %1}, %2;" : "=f"(x), "=f"(y) : "l"(v));
}

// ---------------- init ----------------
__global__ void zero_state() {
    int i = blockIdx.x * blockDim.x + threadIdx.x;
    if (i < 3*BH) { g_h[i] = 0.f; g_c[i] = 0.f; }
    if (i < BB*2*HH) g_qstar[i] = 0.f;
}

__global__ void seg_bounds(const int* __restrict__ idx) {
    int b = threadIdx.x;
    if (b > BB) return;
    int lo = 0, hi = NN;
    while (lo < hi) { int mid = (lo + hi) >> 1; if (idx[mid] < b) lo = mid + 1; else hi = mid; }
    g_seg[b] = lo;
}

// ---------------- FNN GEMM: round-2 proven FFMA2 version ----------------
template<int PHASE>
__global__ void __launch_bounds__(256, 2)
fnn_gemm(const float* __restrict__ Ax, const float* __restrict__ W,
         const float* __restrict__ bias) {
    const float* A = (PHASE == 0) ? Ax : g_y1;
    float* C = (PHASE == 0) ? g_y1 : g_hfeat;
    __shared__ float As[16*132];   // [k][m], padded stride 132
    __shared__ float Bs[16*128];   // [k][n]
    int tid = threadIdx.x;
    int m0 = blockIdx.x * 128;
    int n0 = blockIdx.y * 128;
    int tx = tid & 15, ty = tid >> 4;
    int c0 = tx * 8, r0 = ty * 8;
    int arow = tid >> 2;           // 0..63
    int akq  = (tid & 3) * 4;      // 0,4,8,12
    int bk   = tid >> 5;           // 0..7
    int bnq  = (tid & 31) * 4;

    ull acc[8][4];                 // 8 rows x 4 col-pairs (packed f32x2)
    #pragma unroll
    for (int i = 0; i < 8; i++)
        #pragma unroll
        for (int j = 0; j < 4; j++) acc[i][j] = 0ull;

    float4 pa0, pa1, pb0, pb1;
    {
        int gm0 = m0 + arow, gm1 = m0 + arow + 64;
        pa0 = (gm0 < NN) ? *(const float4*)&A[(size_t)gm0*DD + akq] : make_float4(0,0,0,0);
        pa1 = (gm1 < NN) ? *(const float4*)&A[(size_t)gm1*DD + akq] : make_float4(0,0,0,0);
        pb0 = *(const float4*)&W[(size_t)bk*HH + n0 + bnq];
        pb1 = *(const float4*)&W[(size_t)(bk+8)*HH + n0 + bnq];
    }
    for (int kt = 0; kt < DD; kt += 16) {
        As[(akq+0)*132+arow] = pa0.x; As[(akq+1)*132+arow] = pa0.y;
        As[(akq+2)*132+arow] = pa0.z; As[(akq+3)*132+arow] = pa0.w;
        As[(akq+0)*132+arow+64] = pa1.x; As[(akq+1)*132+arow+64] = pa1.y;
        As[(akq+2)*132+arow+64] = pa1.z; As[(akq+3)*132+arow+64] = pa1.w;
        *(float4*)&Bs[bk*128 + bnq]     = pb0;
        *(float4*)&Bs[(bk+8)*128 + bnq] = pb1;
        __syncthreads();
        int kn = kt + 16;
        if (kn < DD) {
            int gm0 = m0 + arow, gm1 = m0 + arow + 64;
            pa0 = (gm0 < NN) ? *(const float4*)&A[(size_t)gm0*DD + kn + akq] : make_float4(0,0,0,0);
            pa1 = (gm1 < NN) ? *(const float4*)&A[(size_t)gm1*DD + kn + akq] : make_float4(0,0,0,0);
            pb0 = *(const float4*)&W[(size_t)(kn+bk)*HH + n0 + bnq];
            pb1 = *(const float4*)&W[(size_t)(kn+bk+8)*HH + n0 + bnq];
        }
        #pragma unroll
        for (int k = 0; k < 16; k++) {
            float a[8];
            *(float4*)&a[0] = *(const float4*)&As[k*132 + r0];
            *(float4*)&a[4] = *(const float4*)&As[k*132 + r0 + 4];
            ulonglong2 bq0 = *(const ulonglong2*)&Bs[k*128 + c0];
            ulonglong2 bq1 = *(const ulonglong2*)&Bs[k*128 + c0 + 4];
            ull bp0 = bq0.x, bp1 = bq0.y, bp2 = bq1.x, bp3 = bq1.y;
            #pragma unroll
            for (int i = 0; i < 8; i++) {
                ull ap = bcast2(a[i]);
                ffma2(acc[i][0], ap, bp0);
                ffma2(acc[i][1], ap, bp1);
                ffma2(acc[i][2], ap, bp2);
                ffma2(acc[i][3], ap, bp3);
            }
        }
        __syncthreads();
    }
    float bv[8];
    #pragma unroll
    for (int j = 0; j < 8; j++) bv[j] = bias[n0 + c0 + j];
    #pragma unroll
    for (int i = 0; i < 8; i++) {
        int gm = m0 + r0 + i;
        if (gm < NN) {
            float o[8];
            #pragma unroll
            for (int j = 0; j < 4; j++) {
                float x, y;
                unpack2(acc[i][j], x, y);
                float v0 = x + bv[2*j], v1 = y + bv[2*j+1];
                if (PHASE == 0) {
                    v0 = (v0 > 0.f) ? v0 : expm1f(v0);
                    v1 = (v1 > 0.f) ? v1 : expm1f(v1);
                }
                o[2*j] = v0; o[2*j+1] = v1;
            }
            *(float4*)&C[(size_t)gm*HH + n0 + c0]     = *(float4*)&o[0];
            *(float4*)&C[(size_t)gm*HH + n0 + c0 + 4] = *(float4*)&o[4];
        }
    }
}

// ---------------- LSTM gates (round-2 proven) ----------------
__global__ void __launch_bounds__(128)
lstm_gates(int layer,
           const float* __restrict__ Wih, const float* __restrict__ Whh,
           const float* __restrict__ bih, const float* __restrict__ bhh) {
    __shared__ float As[8*768];
    __shared__ float Ws[32*68];
    const int K1 = (layer == 0) ? 2*HH : HH;
    const int K  = K1 + HH;
    const float* xin = (layer == 0) ? g_qstar : (g_h + (layer-1)*BH);
    const float* hin = g_h + layer*BH;
    int tid = threadIdx.x;
    int b0 = blockIdx.x * 8;
    int n0 = blockIdx.y * 64;
    for (int idx = tid; idx < 8*K; idx += 128) {
        int r = idx / K, k = idx - r*K;
        As[idx] = (k < K1) ? xin[(b0+r)*K1 + k] : hin[(b0+r)*HH + (k - K1)];
    }
    __syncthreads();
    int tx = tid & 15, ty = tid >> 4;
    int c0 = tx * 4;
    int wj = tid >> 3;
    int wk = (tid & 7) * 4;
    float acc[4] = {0.f, 0.f, 0.f, 0.f};
    for (int kt = 0; kt < K; kt += 32) {
        const float* Wsrc; int stride, kc;
        if (kt < K1) { Wsrc = Wih; stride = K1; kc = kt + wk; }
        else         { Wsrc = Whh; stride = HH; kc = kt - K1 + wk; }
        #pragma unroll
        for (int p = 0; p < 4; p++) {
            int j = p*16 + wj;
            float4 v = *(const float4*)&Wsrc[(size_t)(n0+j)*stride + kc];
            Ws[(wk+0)*68+j] = v.x; Ws[(wk+1)*68+j] = v.y;
            Ws[(wk+2)*68+j] = v.z; Ws[(wk+3)*68+j] = v.w;
        }
        __syncthreads();
        const float* arow = As + ty*K + kt;
        #pragma unroll
        for (int k = 0; k < 32; k++) {
            float a = arow[k];
            float4 bv = *(const float4*)&Ws[k*68 + c0];
            acc[0] = fmaf(a, bv.x, acc[0]);
            acc[1] = fmaf(a, bv.y, acc[1]);
            acc[2] = fmaf(a, bv.z, acc[2]);
            acc[3] = fmaf(a, bv.w, acc[3]);
        }
        __syncthreads();
    }
    int gb = b0 + ty;
    #pragma unroll
    for (int j = 0; j < 4; j++) {
        int gc = n0 + c0 + j;
        g_gates[gb*G4H + gc] = acc[j] + bih[gc] + bhh[gc];
    }
}

__global__ void lstm_cell(int layer) {
    int b = blockIdx.x, t = threadIdx.x;
    float* h = g_h + layer*BH;
    float* c = g_c + layer*BH;
    const float* g = g_gates + b*G4H;
    float gi = g[t], gf = g[HH + t], gg = g[2*HH + t], go = g[3*HH + t];
    float cn = sigf(gf) * c[b*HH + t] + sigf(gi) * tanhf(gg);
    float hn = sigf(go) * tanhf(cn);
    c[b*HH + t] = cn;
    h[b*HH + t] = hn;
    if (layer == 2) g_qstar[b*2*HH + t] = hn;
}

// ---------------- fused flash-style segment attention ----------------
// grid (BB, NCHUNK), 256 threads. One hfeat pass: dot + online-softmax + weighted sum.
__global__ void __launch_bounds__(256)
attn_fused() {
    __shared__ float q[HH];
    __shared__ float se[TS];
    __shared__ float sw[TS];
    int b = blockIdx.x, p = blockIdx.y, t = threadIdx.x;
    int lane = t & 31, wid = t >> 5;
    q[t] = g_h[2*BH + b*HH + t];
    __syncthreads();
    int s = g_seg[b], e = g_seg[b+1], len = e - s;
    int c0 = s + (int)(((long long)len * p) / NCHUNK);
    int c1 = s + (int)(((long long)len * (p + 1)) / NCHUNK);

    float M = -INFINITY, S = 0.f, r = 0.f;
    for (int t0 = c0; t0 < c1; t0 += TS) {
        int tl = min(TS, c1 - t0);
        // pass A: warp per row -> se[i]
        for (int i = wid; i < tl; i += 8) {
            const float* row = g_hfeat + (size_t)(t0 + i) * HH;
            float sd = 0.f;
            #pragma unroll
            for (int j = 0; j < 8; j++) sd = fmaf(row[lane + 32*j], q[lane + 32*j], sd);
            #pragma unroll
            for (int o = 16; o > 0; o >>= 1) sd += __shfl_xor_sync(0xffffffffu, sd, o);
            if (lane == 0) se[i] = sd;
        }
        __syncthreads();
        // tile max (redundant per-thread, deterministic)
        float mloc = -INFINITY;
        for (int i = 0; i < tl; i++) mloc = fmaxf(mloc, se[i]);
        float newM = fmaxf(M, mloc);
        float factor = expf(M - newM);   // first tile: exp(-inf)=0, r=S=0 anyway
        if (t < tl) sw[t] = expf(se[t] - newM);
        r *= factor; S *= factor; M = newM;
        __syncthreads();
        // pass B: rows re-read from L1; thread t owns feature t
        for (int i = 0; i < tl; i++) {
            float w = sw[i];
            S += w;
            r = fmaf(w, g_hfeat[(size_t)(t0 + i) * HH + t], r);
        }
        __syncthreads();
    }
    g_rpart[(size_t)(b * NCHUNK + p) * HH + t] = r;
    if (t == 0) { g_spart[b * NCHUNK + p] = S; g_mpart[b * NCHUNK + p] = M; }
}

// combine partials with max-rescale -> r part of q_star
__global__ void __launch_bounds__(256)
attn_combine() {
    __shared__ float sm8[NCHUNK], ss8[NCHUNK];
    int b = blockIdx.x, t = threadIdx.x;
    if (t < NCHUNK) {
        sm8[t] = g_mpart[b * NCHUNK + t];
        ss8[t] = g_spart[b * NCHUNK + t];
    }
    __syncthreads();
    float Mg = -INFINITY;
    #pragma unroll
    for (int p = 0; p < NCHUNK; p++) Mg = fmaxf(Mg, sm8[p]);
    if (!isfinite(Mg)) Mg = 0.f;   // empty-segment guard (matches reference)
    float S = 0.f, r = 0.f;
    #pragma unroll
    for (int p = 0; p < NCHUNK; p++) {
        float f = expf(sm8[p] - Mg);   // -inf partial -> 0
        S = fmaf(ss8[p], f, S);
        r = fmaf(g_rpart[(size_t)(b * NCHUNK + p) * HH + t], f, r);
    }
    g_qstar[b * 2 * HH + HH + t] = r / (S + 1e-16f);
}

// ---------------- output projection ----------------
__global__ void out_proj(const float* __restrict__ W, const float* __restrict__ bvec,
                         float* __restrict__ out) {
    __shared__ float qrow[2*HH];
    int b = blockIdx.x, t = threadIdx.x;    // 128 threads
    #pragma unroll
    for (int i = 0; i < 4; i++) qrow[t + i*128] = g_qstar[b*2*HH + t + i*128];
    __syncthreads();
    float acc = 0.f;
    #pragma unroll 8
    for (int k = 0; k < 2*HH; k++) acc = fmaf(qrow[k], W[k*EE + t], acc);
    out[b*EE + t] = acc + bvec[t];
}

// ---------------- launch ----------------
extern "C" void kernel_launch(void* const* d_in, const int* in_sizes, int n_in,
                              void* d_out, int out_size) {
    const float* x    = (const float*)d_in[0];
    const int*   bidx = (const int*)  d_in[1];
    const float* W1   = (const float*)d_in[2];
    const float* b1   = (const float*)d_in[3];
    const float* W2   = (const float*)d_in[4];
    const float* b2   = (const float*)d_in[5];
    const float* Wih[3] = {(const float*)d_in[6],  (const float*)d_in[10], (const float*)d_in[14]};
    const float* Whh[3] = {(const float*)d_in[7],  (const float*)d_in[11], (const float*)d_in[15]};
    const float* bih[3] = {(const float*)d_in[8],  (const float*)d_in[12], (const float*)d_in[16]};
    const float* bhh[3] = {(const float*)d_in[9],  (const float*)d_in[13], (const float*)d_in[17]};
    const float* outW = (const float*)d_in[18];
    const float* outb = (const float*)d_in[19];
    float* out = (float*)d_out;

    zero_state<<<(3*BH + 255)/256, 256>>>();
    seg_bounds<<<1, 256>>>(bidx);

    dim3 gfnn((NN + 127)/128, HH/128);
    fnn_gemm<0><<<gfnn, 256>>>(x, W1, b1);
    fnn_gemm<1><<<gfnn, 256>>>(x, W2, b2);   // A ignored in phase 1 (reads g_y1)

    dim3 gg(BB/8, G4H/64);
    dim3 gw(BB, NCHUNK);
    for (int s = 0; s < NSTEPS; s++) {
        for (int l = 0; l < 3; l++) {
            lstm_gates<<<gg, 128>>>(l, Wih[l], Whh[l], bih[l], bhh[l]);
            lstm_cell<<<BB, HH>>>(l);
        }
        attn_fused<<<gw, 256>>>();
        attn_combine<<<BB, 256>>>();
    }
    out_proj<<<BB, EE>>>(outW, outb, out);
}

// round 10
// speedup vs baseline: 1.6392x; 1.1145x over previous
#include <cuda_runtime.h>
#include <cuda_bf16.h>
#include <math.h>
#include <stdint.h>

#define NN 100000
#define DD 256
#define HH 256
#define BB 128
#define EE 128
#define NSTEPS 5
#define BH (BB*HH)
#define NCHUNK 16
#define TS 64

typedef unsigned long long ull;

// ---------------- scratch (static device globals; no allocations) ----------------
__device__ float g_y1[(size_t)NN*HH];              // FNN intermediate (fp32)
__device__ __nv_bfloat162 g_hfb16[(size_t)NN*HH/2]; // FNN output, bf16 packed
__device__ float g_h[2*3*BH];                      // ping-pong [parity][layer]
__device__ float g_c[2*3*BH];
__device__ float g_qstar[BB*2*HH];
__device__ float g_rpart[(size_t)BB*NCHUNK*HH];
__device__ float g_spart[BB*NCHUNK];
__device__ float g_mpart[BB*NCHUNK];
__device__ int   g_seg[BB+1];

// ---------------- helpers ----------------
__device__ __forceinline__ float sigf(float x) { return 1.f / (1.f + expf(-x)); }

__device__ __forceinline__ void ffma2(ull &d, ull a, ull b) {
    asm("fma.rn.f32x2 %0, %1, %2, %3;" : "=l"(d) : "l"(a), "l"(b), "l"(d));
}
__device__ __forceinline__ ull bcast2(float a) {
    ull r;
    asm("mov.b64 %0, {%1, %1};" : "=l"(r) : "f"(a));
    return r;
}
__device__ __forceinline__ void unpack2(ull v, float &x, float &y) {
    asm("mov.b64 {%0, %1}, %2;" : "=f"(x), "=f"(y) : "l"(v));
}

// ---------------- init ----------------
__global__ void zero_state() {
    int i = blockIdx.x * blockDim.x + threadIdx.x;
    if (i < 2*3*BH) { g_h[i] = 0.f; g_c[i] = 0.f; }
    if (i < BB*2*HH) g_qstar[i] = 0.f;
}

__global__ void seg_bounds(const int* __restrict__ idx) {
    int b = threadIdx.x;
    if (b > BB) return;
    int lo = 0, hi = NN;
    while (lo < hi) { int mid = (lo + hi) >> 1; if (idx[mid] < b) lo = mid + 1; else hi = mid; }
    g_seg[b] = lo;
}

// ---------------- FNN GEMM: proven FFMA2 kernel; phase 1 writes bf16 ----------------
template<int PHASE>
__global__ void __launch_bounds__(256, 2)
fnn_gemm(const float* __restrict__ Ax, const float* __restrict__ W,
         const float* __restrict__ bias) {
    const float* A = (PHASE == 0) ? Ax : g_y1;
    __shared__ float As[16*132];   // [k][m], padded stride 132
    __shared__ float Bs[16*128];   // [k][n]
    int tid = threadIdx.x;
    int m0 = blockIdx.x * 128;
    int n0 = blockIdx.y * 128;
    int tx = tid & 15, ty = tid >> 4;
    int c0 = tx * 8, r0 = ty * 8;
    int arow = tid >> 2;
    int akq  = (tid & 3) * 4;
    int bk   = tid >> 5;
    int bnq  = (tid & 31) * 4;

    ull acc[8][4];
    #pragma unroll
    for (int i = 0; i < 8; i++)
        #pragma unroll
        for (int j = 0; j < 4; j++) acc[i][j] = 0ull;

    float4 pa0, pa1, pb0, pb1;
    {
        int gm0 = m0 + arow, gm1 = m0 + arow + 64;
        pa0 = (gm0 < NN) ? *(const float4*)&A[(size_t)gm0*DD + akq] : make_float4(0,0,0,0);
        pa1 = (gm1 < NN) ? *(const float4*)&A[(size_t)gm1*DD + akq] : make_float4(0,0,0,0);
        pb0 = *(const float4*)&W[(size_t)bk*HH + n0 + bnq];
        pb1 = *(const float4*)&W[(size_t)(bk+8)*HH + n0 + bnq];
    }
    for (int kt = 0; kt < DD; kt += 16) {
        As[(akq+0)*132+arow] = pa0.x; As[(akq+1)*132+arow] = pa0.y;
        As[(akq+2)*132+arow] = pa0.z; As[(akq+3)*132+arow] = pa0.w;
        As[(akq+0)*132+arow+64] = pa1.x; As[(akq+1)*132+arow+64] = pa1.y;
        As[(akq+2)*132+arow+64] = pa1.z; As[(akq+3)*132+arow+64] = pa1.w;
        *(float4*)&Bs[bk*128 + bnq]     = pb0;
        *(float4*)&Bs[(bk+8)*128 + bnq] = pb1;
        __syncthreads();
        int kn = kt + 16;
        if (kn < DD) {
            int gm0 = m0 + arow, gm1 = m0 + arow + 64;
            pa0 = (gm0 < NN) ? *(const float4*)&A[(size_t)gm0*DD + kn + akq] : make_float4(0,0,0,0);
            pa1 = (gm1 < NN) ? *(const float4*)&A[(size_t)gm1*DD + kn + akq] : make_float4(0,0,0,0);
            pb0 = *(const float4*)&W[(size_t)(kn+bk)*HH + n0 + bnq];
            pb1 = *(const float4*)&W[(size_t)(kn+bk+8)*HH + n0 + bnq];
        }
        #pragma unroll
        for (int k = 0; k < 16; k++) {
            float a[8];
            *(float4*)&a[0] = *(const float4*)&As[k*132 + r0];
            *(float4*)&a[4] = *(const float4*)&As[k*132 + r0 + 4];
            ulonglong2 bq0 = *(const ulonglong2*)&Bs[k*128 + c0];
            ulonglong2 bq1 = *(const ulonglong2*)&Bs[k*128 + c0 + 4];
            ull bp0 = bq0.x, bp1 = bq0.y, bp2 = bq1.x, bp3 = bq1.y;
            #pragma unroll
            for (int i = 0; i < 8; i++) {
                ull ap = bcast2(a[i]);
                ffma2(acc[i][0], ap, bp0);
                ffma2(acc[i][1], ap, bp1);
                ffma2(acc[i][2], ap, bp2);
                ffma2(acc[i][3], ap, bp3);
            }
        }
        __syncthreads();
    }
    float bv[8];
    #pragma unroll
    for (int j = 0; j < 8; j++) bv[j] = bias[n0 + c0 + j];
    #pragma unroll
    for (int i = 0; i < 8; i++) {
        int gm = m0 + r0 + i;
        if (gm < NN) {
            float o[8];
            #pragma unroll
            for (int j = 0; j < 4; j++) {
                float x, y;
                unpack2(acc[i][j], x, y);
                float v0 = x + bv[2*j], v1 = y + bv[2*j+1];
                if (PHASE == 0) {
                    v0 = (v0 > 0.f) ? v0 : expm1f(v0);
                    v1 = (v1 > 0.f) ? v1 : expm1f(v1);
                }
                o[2*j] = v0; o[2*j+1] = v1;
            }
            if (PHASE == 0) {
                *(float4*)&g_y1[(size_t)gm*HH + n0 + c0]     = *(float4*)&o[0];
                *(float4*)&g_y1[(size_t)gm*HH + n0 + c0 + 4] = *(float4*)&o[4];
            } else {
                __nv_bfloat162 p0 = __float22bfloat162_rn(make_float2(o[0], o[1]));
                __nv_bfloat162 p1 = __float22bfloat162_rn(make_float2(o[2], o[3]));
                __nv_bfloat162 p2 = __float22bfloat162_rn(make_float2(o[4], o[5]));
                __nv_bfloat162 p3 = __float22bfloat162_rn(make_float2(o[6], o[7]));
                uint4 pk;
                pk.x = *(uint32_t*)&p0; pk.y = *(uint32_t*)&p1;
                pk.z = *(uint32_t*)&p2; pk.w = *(uint32_t*)&p3;
                *(uint4*)&g_hfb16[((size_t)gm*HH + n0 + c0) >> 1] = pk;
            }
        }
    }
}

// ---------------- fused LSTM layer: gates + cell in one kernel ----------------
// grid (BB/8, HH/16), 128 threads. Each thread computes all 4 gates (i,f,g,o)
// of one (batch, h-column) and applies the cell update. Ping-pong h/c on parity.
__global__ void __launch_bounds__(128)
lstm_fused(int layer, int pr,
           const float* __restrict__ Wih, const float* __restrict__ Whh,
           const float* __restrict__ bih, const float* __restrict__ bhh) {
    __shared__ float As[8*768];     // [r][k], compact stride K
    __shared__ float Ws[32*68];     // [k][j], padded; j = 4*hcol_local + gate
    const int K1 = (layer == 0) ? 2*HH : HH;
    const int K  = K1 + HH;
    const int pw = pr ^ 1;
    const float* xin = (layer == 0) ? g_qstar : (g_h + (size_t)(pw*3 + (layer-1))*BH);
    const float* hin = g_h + (size_t)(pr*3 + layer)*BH;
    const float* cin = g_c + (size_t)(pr*3 + layer)*BH;
    float* hout = g_h + (size_t)(pw*3 + layer)*BH;
    float* cout = g_c + (size_t)(pw*3 + layer)*BH;
    int tid = threadIdx.x;
    int b0 = blockIdx.x * 8;
    int t0 = blockIdx.y * 16;       // h-column base
    for (int idx = tid; idx < 8*K; idx += 128) {
        int r = idx / K, k = idx - r*K;
        As[idx] = (k < K1) ? xin[(b0+r)*K1 + k] : hin[(b0+r)*HH + (k - K1)];
    }
    __syncthreads();
    int tx = tid & 15, ty = tid >> 4;   // ty = batch row 0..7
    int c0 = tx * 4;
    int wj = tid >> 3;                  // 0..15
    int wk = (tid & 7) * 4;             // 0,4,..28
    float acc[4] = {0.f, 0.f, 0.f, 0.f};
    for (int kt = 0; kt < K; kt += 32) {
        const float* Wsrc; int stride, kc;
        if (kt < K1) { Wsrc = Wih; stride = K1; kc = kt + wk; }
        else         { Wsrc = Whh; stride = HH; kc = kt - K1 + wk; }
        #pragma unroll
        for (int p = 0; p < 4; p++) {
            int j = p*16 + wj;
            int grow = (j & 3) * HH + t0 + (j >> 2);   // gate-interleaved
            float4 v = *(const float4*)&Wsrc[(size_t)grow*stride + kc];
            Ws[(wk+0)*68+j] = v.x; Ws[(wk+1)*68+j] = v.y;
            Ws[(wk+2)*68+j] = v.z; Ws[(wk+3)*68+j] = v.w;
        }
        __syncthreads();
        const float* arow = As + ty*K + kt;
        #pragma unroll
        for (int k = 0; k < 32; k++) {
            float a = arow[k];
            float4 bv = *(const float4*)&Ws[k*68 + c0];
            acc[0] = fmaf(a, bv.x, acc[0]);
            acc[1] = fmaf(a, bv.y, acc[1]);
            acc[2] = fmaf(a, bv.z, acc[2]);
            acc[3] = fmaf(a, bv.w, acc[3]);
        }
        __syncthreads();
    }
    int b = b0 + ty, hcol = t0 + tx;
    float gi = acc[0] + bih[hcol]        + bhh[hcol];
    float gf = acc[1] + bih[HH + hcol]   + bhh[HH + hcol];
    float gg = acc[2] + bih[2*HH + hcol] + bhh[2*HH + hcol];
    float go = acc[3] + bih[3*HH + hcol] + bhh[3*HH + hcol];
    float cn = sigf(gf) * cin[b*HH + hcol] + sigf(gi) * tanhf(gg);
    float hn = sigf(go) * tanhf(cn);
    cout[b*HH + hcol] = cn;
    hout[b*HH + hcol] = hn;
    if (layer == 2) g_qstar[b*2*HH + hcol] = hn;
}

// ---------------- fused flash-style segment attention (bf16 hfeat) ----------------
// grid (BB, NCHUNK), 256 threads.
__global__ void __launch_bounds__(256)
attn_fused(int pw) {
    __shared__ float q[HH];
    __shared__ float se[TS];
    __shared__ float sw[TS];
    __shared__ float2 sacc[2][128];
    int b = blockIdx.x, p = blockIdx.y, t = threadIdx.x;
    int lane = t & 31, wid = t >> 5;
    q[t] = g_h[(size_t)(pw*3 + 2)*BH + b*HH + t];
    __syncthreads();
    int s = g_seg[b], e = g_seg[b+1], len = e - s;
    int c0 = s + (int)(((long long)len * p) / NCHUNK);
    int c1 = s + (int)(((long long)len * (p + 1)) / NCHUNK);

    int half = t >> 7, tt = t & 127;
    float M = -INFINITY, S = 0.f;
    float2 acc = make_float2(0.f, 0.f);
    for (int t0 = c0; t0 < c1; t0 += TS) {
        int tl = min(TS, c1 - t0);
        // pass A: warp per row -> se[i]; lane loads 8 bf16 (16B)
        for (int i = wid; i < tl; i += 8) {
            uint4 v = ((const uint4*)(g_hfb16 + (size_t)(t0 + i) * (HH/2)))[lane];
            float2 h0 = __bfloat1622float2(*(__nv_bfloat162*)&v.x);
            float2 h1 = __bfloat1622float2(*(__nv_bfloat162*)&v.y);
            float2 h2 = __bfloat1622float2(*(__nv_bfloat162*)&v.z);
            float2 h3 = __bfloat1622float2(*(__nv_bfloat162*)&v.w);
            const float* qb = q + lane * 8;
            float sd = 0.f;
            sd = fmaf(h0.x, qb[0], sd); sd = fmaf(h0.y, qb[1], sd);
            sd = fmaf(h1.x, qb[2], sd); sd = fmaf(h1.y, qb[3], sd);
            sd = fmaf(h2.x, qb[4], sd); sd = fmaf(h2.y, qb[5], sd);
            sd = fmaf(h3.x, qb[6], sd); sd = fmaf(h3.y, qb[7], sd);
            #pragma unroll
            for (int o = 16; o > 0; o >>= 1) sd += __shfl_xor_sync(0xffffffffu, sd, o);
            if (lane == 0) se[i] = sd;
        }
        __syncthreads();
        float mloc = -INFINITY;
        for (int i = 0; i < tl; i++) mloc = fmaxf(mloc, se[i]);
        float newM = fmaxf(M, mloc);
        float factor = expf(M - newM);
        if (t < tl) sw[t] = expf(se[t] - newM);
        acc.x *= factor; acc.y *= factor; S *= factor; M = newM;
        __syncthreads();
        // S (every thread, deterministic) + pass B (rows split between halves)
        for (int i = 0; i < tl; i++) S += sw[i];
        for (int i = half; i < tl; i += 2) {
            float w = sw[i];
            float2 hv = __bfloat1622float2(g_hfb16[(size_t)(t0 + i) * (HH/2) + tt]);
            acc.x = fmaf(w, hv.x, acc.x);
            acc.y = fmaf(w, hv.y, acc.y);
        }
        __syncthreads();
    }
    sacc[half][tt] = acc;
    __syncthreads();
    if (t < 128) {
        float2 a0 = sacc[0][t], a1 = sacc[1][t];
        float* dst = g_rpart + (size_t)(b * NCHUNK + p) * HH;
        dst[2*t]   = a0.x + a1.x;
        dst[2*t+1] = a0.y + a1.y;
    }
    if (t == 0) { g_spart[b * NCHUNK + p] = S; g_mpart[b * NCHUNK + p] = M; }
}

// combine partials with max-rescale -> r part of q_star
__global__ void __launch_bounds__(256)
attn_combine() {
    __shared__ float sm8[NCHUNK], ss8[NCHUNK];
    int b = blockIdx.x, t = threadIdx.x;
    if (t < NCHUNK) {
        sm8[t] = g_mpart[b * NCHUNK + t];
        ss8[t] = g_spart[b * NCHUNK + t];
    }
    __syncthreads();
    float Mg = -INFINITY;
    #pragma unroll
    for (int p = 0; p < NCHUNK; p++) Mg = fmaxf(Mg, sm8[p]);
    if (!isfinite(Mg)) Mg = 0.f;   // empty-segment guard (matches reference)
    float S = 0.f, r = 0.f;
    #pragma unroll
    for (int p = 0; p < NCHUNK; p++) {
        float f = expf(sm8[p] - Mg);
        S = fmaf(ss8[p], f, S);
        r = fmaf(g_rpart[(size_t)(b * NCHUNK + p) * HH + t], f, r);
    }
    g_qstar[b * 2 * HH + HH + t] = r / (S + 1e-16f);
}

// ---------------- output projection ----------------
__global__ void out_proj(const float* __restrict__ W, const float* __restrict__ bvec,
                         float* __restrict__ out) {
    __shared__ float qrow[2*HH];
    int b = blockIdx.x, t = threadIdx.x;    // 128 threads
    #pragma unroll
    for (int i = 0; i < 4; i++) qrow[t + i*128] = g_qstar[b*2*HH + t + i*128];
    __syncthreads();
    float acc = 0.f;
    #pragma unroll 8
    for (int k = 0; k < 2*HH; k++) acc = fmaf(qrow[k], W[k*EE + t], acc);
    out[b*EE + t] = acc + bvec[t];
}

// ---------------- launch ----------------
extern "C" void kernel_launch(void* const* d_in, const int* in_sizes, int n_in,
                              void* d_out, int out_size) {
    const float* x    = (const float*)d_in[0];
    const int*   bidx = (const int*)  d_in[1];
    const float* W1   = (const float*)d_in[2];
    const float* b1   = (const float*)d_in[3];
    const float* W2   = (const float*)d_in[4];
    const float* b2   = (const float*)d_in[5];
    const float* Wih[3] = {(const float*)d_in[6],  (const float*)d_in[10], (const float*)d_in[14]};
    const float* Whh[3] = {(const float*)d_in[7],  (const float*)d_in[11], (const float*)d_in[15]};
    const float* bih[3] = {(const float*)d_in[8],  (const float*)d_in[12], (const float*)d_in[16]};
    const float* bhh[3] = {(const float*)d_in[9],  (const float*)d_in[13], (const float*)d_in[17]};
    const float* outW = (const float*)d_in[18];
    const float* outb = (const float*)d_in[19];
    float* out = (float*)d_out;

    zero_state<<<(2*3*BH + 255)/256, 256>>>();
    seg_bounds<<<1, 256>>>(bidx);

    dim3 gfnn((NN + 127)/128, HH/128);
    fnn_gemm<0><<<gfnn, 256>>>(x, W1, b1);
    fnn_gemm<1><<<gfnn, 256>>>(x, W2, b2);   // A ignored in phase 1 (reads g_y1)

    dim3 gl(BB/8, HH/16);
    dim3 gw(BB, NCHUNK);
    for (int s = 0; s < NSTEPS; s++) {
        int pr = s & 1;
        for (int l = 0; l < 3; l++)
            lstm_fused<<<gl, 128>>>(l, pr, Wih[l], Whh[l], bih[l], bhh[l]);
        attn_fused<<<gw, 256>>>(pr ^ 1);
        attn_combine<<<BB, 256>>>();
    }
    out_proj<<<BB, EE>>>(outW, outb, out);
}